// round 2
// baseline (speedup 1.0000x reference)
#include <cuda_runtime.h>
#include <math.h>

#define NBL   4096          // B*L
#define HHH   16            // heads
#define DDD   64
#define HIDD  1024
#define OUTC  128           // 2*D hidden layer width
#define KEXT  268           // 256 branch rows + 12 stat rows
#define KCH   67            // KEXT/4
#define XPAD  272           // padded per-head x row (multiple of 4)

typedef unsigned long long ull;

// scratch (device globals: allocation-free rule)
__device__ __align__(16) float g_Hc[NBL * OUTC];   // hidden @ W1[0:1024] + b1
__device__ __align__(16) float g_SW[12 * OUTC];    // stat-row column sums

// ---------- packed f32x2 helpers ----------
__device__ __forceinline__ ull pack2(float a, float b) {
    ull r;
    asm("mov.b64 %0, {%1, %2};" : "=l"(r)
        : "r"(__float_as_uint(a)), "r"(__float_as_uint(b)));
    return r;
}
__device__ __forceinline__ ull fma2(ull a, ull b, ull c) {
    ull d;
    asm("fma.rn.f32x2 %0, %1, %2, %3;" : "=l"(d) : "l"(a), "l"(b), "l"(c));
    return d;
}
__device__ __forceinline__ float2 unp2(ull a) {
    unsigned lo, hi;
    asm("mov.b64 {%0, %1}, %2;" : "=r"(lo), "=r"(hi) : "l"(a));
    return make_float2(__uint_as_float(lo), __uint_as_float(hi));
}
__device__ __forceinline__ float gelu_f(float x) {
    return 0.5f * x * (1.0f + erff(x * 0.70710678118654752440f));
}

// ---------------------------------------------------------------------------
// Kernel 1: SW[s][o] = sum_{r=0..63} W1[1024 + s*64 + r][o],  s = p*3 + stat
// ---------------------------------------------------------------------------
__global__ void sw_kernel(const float* __restrict__ W1) {
    int s = blockIdx.x;          // 0..11
    int o = threadIdx.x;         // 0..127
    const float* p = W1 + (size_t)(1024 + s * 64) * OUTC + o;
    float acc = 0.f;
#pragma unroll 8
    for (int r = 0; r < 64; r++) acc += p[(size_t)r * OUTC];
    g_SW[s * OUTC + o] = acc;
}

// ---------------------------------------------------------------------------
// Kernel 2: g_Hc[row][o] = hidden[row][:] @ W1[0:1024][o] + b1[o]
// M=4096, K=1024, N=128. 128 blocks, Mtile=32, Ktile=32, double-buffered.
// ---------------------------------------------------------------------------
__global__ __launch_bounds__(256) void hid_gemm(const float* __restrict__ A,
                                                const float* __restrict__ W1,
                                                const float* __restrict__ b1) {
    __shared__ float As[2][32 * 36];   // padded rows (36 floats, 16B-aligned)
    __shared__ float Bs[2][32 * 128];

    const int tid = threadIdx.x;
    const int m0  = blockIdx.x * 32;
    const int tr  = tid >> 4;          // 0..15 -> rows tr*2, tr*2+1
    const int tc  = tid & 15;          // 0..15 -> cols tc*4..+3 and 64+tc*4..+3

    const int lar = tid >> 3;          // A: tile row 0..31
    const int lac = (tid & 7) << 2;    // A: k offset 0..28
    const int lbr = tid >> 3;          // B: k row 0..31
    const int lbc = (tid & 7) << 2;    // B: col base, + j*32

    const float* Ag = A  + (size_t)(m0 + lar) * HIDD + lac;
    const float* Bg = W1 + (size_t)lbr * OUTC + lbc;

    ull acc[2][4];
#pragma unroll
    for (int i = 0; i < 2; i++)
#pragma unroll
        for (int j = 0; j < 4; j++) acc[i][j] = 0ull;

    // preload chunk 0
    float4 aR  = *(const float4*)(Ag);
    float4 bR0 = *(const float4*)(Bg);
    float4 bR1 = *(const float4*)(Bg + 32);
    float4 bR2 = *(const float4*)(Bg + 64);
    float4 bR3 = *(const float4*)(Bg + 96);
    *(float4*)&As[0][lar * 36 + lac] = aR;
    *(float4*)&Bs[0][lbr * 128 + lbc]      = bR0;
    *(float4*)&Bs[0][lbr * 128 + lbc + 32] = bR1;
    *(float4*)&Bs[0][lbr * 128 + lbc + 64] = bR2;
    *(float4*)&Bs[0][lbr * 128 + lbc + 96] = bR3;
    __syncthreads();

    for (int c = 0; c < 32; c++) {
        if (c + 1 < 32) {
            const float* ag = Ag + (c + 1) * 32;
            const float* bg = Bg + (size_t)(c + 1) * 32 * OUTC;
            aR  = *(const float4*)(ag);
            bR0 = *(const float4*)(bg);
            bR1 = *(const float4*)(bg + 32);
            bR2 = *(const float4*)(bg + 64);
            bR3 = *(const float4*)(bg + 96);
        }
        const float* as = As[c & 1];
        const float* bs = Bs[c & 1];
#pragma unroll
        for (int kk = 0; kk < 32; kk++) {
            float a0 = as[(tr * 2) * 36 + kk];
            float a1 = as[(tr * 2 + 1) * 36 + kk];
            ull a0d = pack2(a0, a0);
            ull a1d = pack2(a1, a1);
            ulonglong2 bl = *(const ulonglong2*)&bs[kk * 128 + tc * 4];
            ulonglong2 bh = *(const ulonglong2*)&bs[kk * 128 + 64 + tc * 4];
            acc[0][0] = fma2(a0d, bl.x, acc[0][0]);
            acc[0][1] = fma2(a0d, bl.y, acc[0][1]);
            acc[0][2] = fma2(a0d, bh.x, acc[0][2]);
            acc[0][3] = fma2(a0d, bh.y, acc[0][3]);
            acc[1][0] = fma2(a1d, bl.x, acc[1][0]);
            acc[1][1] = fma2(a1d, bl.y, acc[1][1]);
            acc[1][2] = fma2(a1d, bh.x, acc[1][2]);
            acc[1][3] = fma2(a1d, bh.y, acc[1][3]);
        }
        __syncthreads();
        if (c + 1 < 32) {
            int nb = (c + 1) & 1;
            *(float4*)&As[nb][lar * 36 + lac] = aR;
            *(float4*)&Bs[nb][lbr * 128 + lbc]      = bR0;
            *(float4*)&Bs[nb][lbr * 128 + lbc + 32] = bR1;
            *(float4*)&Bs[nb][lbr * 128 + lbc + 64] = bR2;
            *(float4*)&Bs[nb][lbr * 128 + lbc + 96] = bR3;
            __syncthreads();
        }
    }

    float4 blo = *(const float4*)(b1 + tc * 4);
    float4 bhi = *(const float4*)(b1 + 64 + tc * 4);
#pragma unroll
    for (int i = 0; i < 2; i++) {
        int row = m0 + tr * 2 + i;
        float2 a = unp2(acc[i][0]), b = unp2(acc[i][1]);
        float2 c2 = unp2(acc[i][2]), d = unp2(acc[i][3]);
        float4 lo = make_float4(a.x + blo.x, a.y + blo.y, b.x + blo.z, b.y + blo.w);
        float4 hi = make_float4(c2.x + bhi.x, c2.y + bhi.y, d.x + bhi.z, d.y + bhi.w);
        *(float4*)&g_Hc[(size_t)row * OUTC + tc * 4]      = lo;
        *(float4*)&g_Hc[(size_t)row * OUTC + 64 + tc * 4] = hi;
    }
}

// ---------------------------------------------------------------------------
// Kernel 3: persistent gate kernel.
// Block: 256 threads (8 warps). Wext[268][128] in smem (branch W1 rows + SW).
// Warp w: row-slot w>>1, head-half w&1 (8 heads). 64 fp32 accs as 32 f32x2.
// ---------------------------------------------------------------------------
__global__ __launch_bounds__(256, 1) void gate_kernel(
    const float* __restrict__ br0, const float* __restrict__ br1,
    const float* __restrict__ br2, const float* __restrict__ br3,
    const float* __restrict__ W1,  const float* __restrict__ W2,
    const float* __restrict__ b2,  const float* __restrict__ eps,
    const float* __restrict__ temp, float* __restrict__ out)
{
    extern __shared__ float smf[];
    float* ws = smf;                       // [KEXT][128]
    float* xs = smf + KEXT * OUTC;         // [4 slots][16 heads][XPAD]

    const int tid = threadIdx.x;

    // cooperative load of Wext: rows 0..255 = W1[1792..2047], rows 256..267 = SW
    {
        const float4* src = (const float4*)(W1 + (size_t)1792 * OUTC);
        float4* dst = (float4*)ws;
        for (int i = tid; i < 256 * OUTC / 4; i += 256) dst[i] = src[i];
        const float4* s2 = (const float4*)g_SW;
        float4* d2 = (float4*)(ws + 256 * OUTC);
        for (int i = tid; i < 12 * OUTC / 4; i += 256) d2[i] = s2[i];
    }

    const int warp = tid >> 5, lane = tid & 31;
    const int slot = warp >> 1, hg = warp & 1;
    const int h_idx = lane >> 2, q = lane & 3;
    const int h_abs = hg * 8 + h_idx;

    float4 w2v[4];
#pragma unroll
    for (int j = 0; j < 4; j++) w2v[j] = ((const float4*)W2)[lane * 4 + j];
    const float4 b2v = *(const float4*)b2;
    __syncthreads();

    const float* brp0 = br0; const float* brp1 = br1;
    const float* brp2 = br2; const float* brp3 = br3;
    float* xw = xs + slot * (HHH * XPAD);

    for (int base = blockIdx.x * 4; base < NBL; base += gridDim.x * 4) {
        const int row = base + slot;          // base multiple of 4, < 4096 -> valid
        __syncwarp();

        // ---- load raw branch data + compute stats from registers ----
        float stt[4][3];
#pragma unroll
        for (int p = 0; p < 4; p++) {
            const float* bp = (p == 0) ? brp0 : (p == 1) ? brp1 : (p == 2) ? brp2 : brp3;
            const float* g = bp + (size_t)row * 1024 + h_abs * 64 + q * 16;
            float sum = 0.f, sq = 0.f, mx = -INFINITY;
#pragma unroll
            for (int j = 0; j < 4; j++) {
                float4 v = *(const float4*)(g + j * 4);
                *(float4*)&xw[h_abs * XPAD + p * 64 + q * 16 + j * 4] = v;
                sum += (v.x + v.y) + (v.z + v.w);
                sq  += v.x * v.x + v.y * v.y + v.z * v.z + v.w * v.w;
                mx = fmaxf(mx, fmaxf(fmaxf(v.x, v.y), fmaxf(v.z, v.w)));
            }
            sum += __shfl_xor_sync(0xffffffffu, sum, 1);
            sum += __shfl_xor_sync(0xffffffffu, sum, 2);
            sq  += __shfl_xor_sync(0xffffffffu, sq, 1);
            sq  += __shfl_xor_sync(0xffffffffu, sq, 2);
            mx = fmaxf(mx, __shfl_xor_sync(0xffffffffu, mx, 1));
            mx = fmaxf(mx, __shfl_xor_sync(0xffffffffu, mx, 2));
            stt[p][0] = sum * (1.f / 64.f);
            stt[p][1] = sqrtf(fmaxf(sq * (1.f / 64.f), 1e-8f));
            stt[p][2] = mx;
        }
        if (q == 0) {
#pragma unroll
            for (int p = 0; p < 4; p++) {
                xw[h_abs * XPAD + 256 + p * 3 + 0] = stt[p][0];
                xw[h_abs * XPAD + 256 + p * 3 + 1] = stt[p][1];
                xw[h_abs * XPAD + 256 + p * 3 + 2] = stt[p][2];
            }
        }
        __syncwarp();

        // ---- init accumulators with hidden contribution (includes b1) ----
        ull acc[8][2];
        {
            ulonglong2 hc = *(const ulonglong2*)(g_Hc + (size_t)row * OUTC + lane * 4);
#pragma unroll
            for (int h = 0; h < 8; h++) { acc[h][0] = hc.x; acc[h][1] = hc.y; }
        }

        const float4* xb[8];
#pragma unroll
        for (int h = 0; h < 8; h++) xb[h] = (const float4*)&xw[(hg * 8 + h) * XPAD];

        // ---- main K loop: 268 = 256 branch + 12 stat rows, chunks of 4 ----
        for (int kc = 0; kc < KCH; kc++) {
            float4 xv[8];
#pragma unroll
            for (int h = 0; h < 8; h++) xv[h] = xb[h][kc];
#pragma unroll
            for (int j = 0; j < 4; j++) {
                ulonglong2 wv = *(const ulonglong2*)&ws[(kc * 4 + j) * OUTC + lane * 4];
#pragma unroll
                for (int h = 0; h < 8; h++) {
                    float xvv = (j == 0) ? xv[h].x : (j == 1) ? xv[h].y
                              : (j == 2) ? xv[h].z : xv[h].w;
                    ull x2 = pack2(xvv, xvv);
                    acc[h][0] = fma2(x2, wv.x, acc[h][0]);
                    acc[h][1] = fma2(x2, wv.y, acc[h][1]);
                }
            }
        }

        // ---- epilogue: gelu, x W2, warp-reduce, softmax/floor ----
        float L0 = 0.f, L1 = 0.f, L2 = 0.f, L3 = 0.f;
#pragma unroll
        for (int h = 0; h < 8; h++) {
            float2 a01 = unp2(acc[h][0]);
            float2 a23 = unp2(acc[h][1]);
            float g0 = gelu_f(a01.x), g1 = gelu_f(a01.y);
            float g2 = gelu_f(a23.x), g3 = gelu_f(a23.y);
            float p0 = g0 * w2v[0].x + g1 * w2v[1].x + g2 * w2v[2].x + g3 * w2v[3].x;
            float p1 = g0 * w2v[0].y + g1 * w2v[1].y + g2 * w2v[2].y + g3 * w2v[3].y;
            float p2 = g0 * w2v[0].z + g1 * w2v[1].z + g2 * w2v[2].z + g3 * w2v[3].z;
            float p3 = g0 * w2v[0].w + g1 * w2v[1].w + g2 * w2v[2].w + g3 * w2v[3].w;
#pragma unroll
            for (int off = 16; off >= 1; off >>= 1) {
                p0 += __shfl_xor_sync(0xffffffffu, p0, off);
                p1 += __shfl_xor_sync(0xffffffffu, p1, off);
                p2 += __shfl_xor_sync(0xffffffffu, p2, off);
                p3 += __shfl_xor_sync(0xffffffffu, p3, off);
            }
            if (lane == h) {
                L0 = p0 + b2v.x; L1 = p1 + b2v.y;
                L2 = p2 + b2v.z; L3 = p3 + b2v.w;
            }
        }
        if (lane < 8) {
            int head = hg * 8 + lane;
            float t = fminf(fmaxf(temp[head], 0.2f), 10.0f);
            float it = 1.f / t;
            float s0 = L0 * it, s1 = L1 * it, s2 = L2 * it, s3 = L3 * it;
            float m = fmaxf(fmaxf(s0, s1), fmaxf(s2, s3));
            float e0 = expf(s0 - m), e1 = expf(s1 - m);
            float e2 = expf(s2 - m), e3 = expf(s3 - m);
            float inv = 1.f / (e0 + e1 + e2 + e3);
            float w0 = e0 * inv, w1 = e1 * inv, w2 = e2 * inv, w3 = e3 * inv;
            float4 ef = *(const float4*)(eps + head * 4);
            w0 = fmaxf(w0, fminf(fmaxf(ef.x, 1e-7f), 0.1f));
            w1 = fmaxf(w1, fminf(fmaxf(ef.y, 1e-7f), 0.1f));
            w2 = fmaxf(w2, fminf(fmaxf(ef.z, 1e-7f), 0.1f));
            w3 = fmaxf(w3, fminf(fmaxf(ef.w, 1e-7f), 0.1f));
            float inv2 = 1.f / (w0 + w1 + w2 + w3);
            float4 o = make_float4(w0 * inv2, w1 * inv2, w2 * inv2, w3 * inv2);
            *(float4*)(out + (size_t)row * 64 + head * 4) = o;
        }
    }
}

// ---------------------------------------------------------------------------
extern "C" void kernel_launch(void* const* d_in, const int* in_sizes, int n_in,
                              void* d_out, int out_size) {
    (void)in_sizes; (void)n_in; (void)out_size;
    const float* hidden = (const float*)d_in[0];
    const float* b0     = (const float*)d_in[1];
    const float* b1br   = (const float*)d_in[2];
    const float* b2br   = (const float*)d_in[3];
    const float* b3br   = (const float*)d_in[4];
    const float* W1     = (const float*)d_in[5];
    const float* b1     = (const float*)d_in[6];
    const float* W2     = (const float*)d_in[7];
    const float* b2     = (const float*)d_in[8];
    const float* eps    = (const float*)d_in[9];
    const float* temp   = (const float*)d_in[10];
    float* out = (float*)d_out;

    const int gate_smem = (KEXT * OUTC + 4 * HHH * XPAD) * (int)sizeof(float); // 206848
    cudaFuncSetAttribute(gate_kernel, cudaFuncAttributeMaxDynamicSharedMemorySize,
                         gate_smem);

    sw_kernel<<<12, 128>>>(W1);
    hid_gemm<<<NBL / 32, 256>>>(hidden, W1, b1);
    gate_kernel<<<148, 256, gate_smem>>>(b0, b1br, b2br, b3br, W1, W2, b2, eps,
                                         temp, out);
}